// round 2
// baseline (speedup 1.0000x reference)
#include <cuda_runtime.h>
#include <cstdint>

// Problem constants
#define TOKENS    512
#define DIM_K     8192
#define DIM_N     8192
#define HASH_SIZE (1 << 22)
#define P_HASH    2038074743LL
#define HASH_RANGE (HASH_SIZE - 32 * 32 + 1)   // 4193281

// GEMM tiling
#define BM 128
#define BN 128
#define BK 16
#define KSTEPS (DIM_K / BK)        // 512
#define KT_HASH (DIM_K / 32)       // 256 hash k-tiles

// Scratch: x transposed to [K][M] so A-tiles are contiguous in M.
__device__ float g_xT[DIM_K * TOKENS];   // 16 MB

// ---------------------------------------------------------------------------
// Kernel 1: transpose x[M][K] -> g_xT[K][M]
// ---------------------------------------------------------------------------
__global__ void transpose_x_kernel(const float* __restrict__ x) {
    __shared__ float t[32][33];
    const int bx = blockIdx.x * 32;  // k
    const int by = blockIdx.y * 32;  // m
    const int tx = threadIdx.x;      // 0..31
    const int ty = threadIdx.y;      // 0..7
#pragma unroll
    for (int i = 0; i < 4; i++) {
        t[ty + i * 8][tx] = x[(size_t)(by + ty + i * 8) * DIM_K + bx + tx];
    }
    __syncthreads();
#pragma unroll
    for (int i = 0; i < 4; i++) {
        g_xT[(size_t)(bx + ty + i * 8) * TOKENS + by + tx] = t[tx][ty + i * 8];
    }
}

// ---------------------------------------------------------------------------
// cp.async helpers
// ---------------------------------------------------------------------------
__device__ __forceinline__ void cp_async_16(void* smem_dst, const void* gmem_src) {
    uint32_t dst = (uint32_t)__cvta_generic_to_shared(smem_dst);
    asm volatile("cp.async.cg.shared.global [%0], [%1], 16;\n"
                 :: "r"(dst), "l"(gmem_src));
}
__device__ __forceinline__ void cp_async_4(void* smem_dst, const void* gmem_src) {
    uint32_t dst = (uint32_t)__cvta_generic_to_shared(smem_dst);
    asm volatile("cp.async.ca.shared.global [%0], [%1], 4;\n"
                 :: "r"(dst), "l"(gmem_src));
}
__device__ __forceinline__ void cp_async_commit() {
    asm volatile("cp.async.commit_group;\n");
}
template <int N>
__device__ __forceinline__ void cp_async_wait() {
    asm volatile("cp.async.wait_group %0;\n" :: "n"(N));
}

// ---------------------------------------------------------------------------
// Robust decode of random_numbers: the reference requests int64, but JAX
// silently downgrades to int32 when x64 isn't enabled at trace time. All
// values are < 2^31, so:
//   int64 little-endian layout as int32: [P, 0, r0, 0, r1, 0, r2, 0, r3, 0]
//   int32 layout:                        [P, r0, r1, r2, r3]
// Discriminate on p[1] == 0 (high word of P in the int64 case).
// ---------------------------------------------------------------------------
__device__ __forceinline__ void decode_rn(const int* p,
                                          long long& R1, long long& R2, long long& R3) {
    if (p[1] == 0) {  // int64 storage
        R1 = (long long)(unsigned)p[2];
        R2 = (long long)(unsigned)p[4];
        R3 = (long long)(unsigned)p[6];
    } else {          // int32 storage
        R1 = (long long)(unsigned)p[1];
        R2 = (long long)(unsigned)p[2];
        R3 = (long long)(unsigned)p[3];
    }
}

// ---------------------------------------------------------------------------
// Kernel 2: hashed-gather GEMM.
//   out[m][n] = sum_k x[m][k] * hw[ start(k/32, n/32) + (k%32)*32 + (n%32) ] + bias[n]
// Static smem: 2*(16*128 + 16*128)*4 + 256*4*4 = 36 KB
// ---------------------------------------------------------------------------
__global__ __launch_bounds__(256, 2)
void rz_gemm_kernel(const float* __restrict__ hw,
                    const float* __restrict__ bias,
                    const int* __restrict__ rn_raw,
                    float* __restrict__ out) {
    __shared__ float Xs[2][BK][BM];        // 16 KB
    __shared__ float Ws[2][BK][BN];        // 16 KB
    __shared__ int   starts[KT_HASH][4];   // 4 KB

    const int tid = threadIdx.x;
    const int nb  = blockIdx.x;            // 0..63  (n block)
    const int mb  = blockIdx.y;            // 0..3   (m block)
    const int m0  = mb * BM;
    const int n0  = nb * BN;

    // ---- Precompute the 4 hash-tile start offsets for all 256 k-tiles ----
    {
        long long R1, R2, R3;
        decode_rn(rn_raw, R1, R2, R3);
        for (int i = tid; i < KT_HASH * 4; i += 256) {
            const int kt = i >> 2;
            const int ns = i & 3;
            long long v = ((long long)kt * R3 + (long long)(nb * 4 + ns) * R2 + R1) % P_HASH;
            starts[kt][ns] = (int)(v % (long long)HASH_RANGE);
        }
    }
    __syncthreads();

    // ---- Tile loaders (cp.async) ----
    // X tile: BK x BM floats from g_xT (contiguous in M) -> 512 float4, 2/thread
    // W tile: BK x BN floats; each n-subtile row block is contiguous in hw.
    auto issue_tile = [&](int ks, int buf) {
#pragma unroll
        for (int u = 0; u < 2; u++) {
            const int ch = tid + u * 256;      // 0..511
            const int kk = ch >> 5;            // 0..15
            const int mq = ch & 31;            // float4 index in row
            cp_async_16(&Xs[buf][kk][mq * 4],
                        &g_xT[(size_t)(ks * BK + kk) * TOKENS + m0 + mq * 4]);
        }
        const int kt   = ks >> 1;              // hash k-tile
        const int half = (ks & 1) << 9;        // +512 floats for the odd half
#pragma unroll
        for (int u = 0; u < 8; u++) {
            const int idx = tid + u * 256;     // 0..2047
            const int ns  = idx >> 9;          // 0..3
            const int rem = idx & 511;         // within half-tile (16 rows * 32)
            const int lk  = rem >> 5;
            const int ln  = rem & 31;
            cp_async_4(&Ws[buf][lk][ns * 32 + ln],
                       &hw[starts[kt][ns] + half + rem]);
        }
        cp_async_commit();
    };

    float acc[8][8];
#pragma unroll
    for (int i = 0; i < 8; i++)
#pragma unroll
        for (int j = 0; j < 8; j++) acc[i][j] = 0.0f;

    const int tx = tid & 15;   // n dir
    const int ty = tid >> 4;   // m dir

    issue_tile(0, 0);

    for (int ks = 0; ks < KSTEPS; ks++) {
        const int buf = ks & 1;
        if (ks + 1 < KSTEPS) {
            issue_tile(ks + 1, buf ^ 1);
            cp_async_wait<1>();
        } else {
            cp_async_wait<0>();
        }
        __syncthreads();

#pragma unroll 8
        for (int kk = 0; kk < BK; kk++) {
            float4 a0 = *(const float4*)&Xs[buf][kk][ty * 8];
            float4 a1 = *(const float4*)&Xs[buf][kk][ty * 8 + 4];
            float4 b0 = *(const float4*)&Ws[buf][kk][tx * 8];
            float4 b1 = *(const float4*)&Ws[buf][kk][tx * 8 + 4];
            float a[8] = {a0.x, a0.y, a0.z, a0.w, a1.x, a1.y, a1.z, a1.w};
            float b[8] = {b0.x, b0.y, b0.z, b0.w, b1.x, b1.y, b1.z, b1.w};
#pragma unroll
            for (int i = 0; i < 8; i++)
#pragma unroll
                for (int j = 0; j < 8; j++) acc[i][j] += a[i] * b[j];
        }
        __syncthreads();
    }

    // ---- Epilogue: add bias, store ----
    float4 bv0 = *(const float4*)&bias[n0 + tx * 8];
    float4 bv1 = *(const float4*)&bias[n0 + tx * 8 + 4];
#pragma unroll
    for (int i = 0; i < 8; i++) {
        const int row = m0 + ty * 8 + i;
        float4 o0, o1;
        o0.x = acc[i][0] + bv0.x;  o0.y = acc[i][1] + bv0.y;
        o0.z = acc[i][2] + bv0.z;  o0.w = acc[i][3] + bv0.w;
        o1.x = acc[i][4] + bv1.x;  o1.y = acc[i][5] + bv1.y;
        o1.z = acc[i][6] + bv1.z;  o1.w = acc[i][7] + bv1.w;
        *(float4*)&out[(size_t)row * DIM_N + n0 + tx * 8]     = o0;
        *(float4*)&out[(size_t)row * DIM_N + n0 + tx * 8 + 4] = o1;
    }
}

// ---------------------------------------------------------------------------
// Launch
// ---------------------------------------------------------------------------
extern "C" void kernel_launch(void* const* d_in, const int* in_sizes, int n_in,
                              void* d_out, int out_size) {
    const float* x    = (const float*)d_in[0];
    const float* hw   = (const float*)d_in[1];
    const float* bias = (const float*)d_in[2];
    const int*   rn   = (const int*)d_in[3];
    float*       out  = (float*)d_out;

    transpose_x_kernel<<<dim3(DIM_K / 32, TOKENS / 32), dim3(32, 8)>>>(x);
    rz_gemm_kernel<<<dim3(DIM_N / BN, TOKENS / BM), 256>>>(hw, bias, rn, out);
}

// round 5
// speedup vs baseline: 1.7493x; 1.7493x over previous
#include <cuda_runtime.h>
#include <cstdint>

// ---------------------------------------------------------------------------
// Problem constants
// ---------------------------------------------------------------------------
#define TOKENS     512
#define DIM_K      8192
#define DIM_N      8192
#define HASH_SIZE  (1 << 22)
#define P_HASH     2038074743LL
#define HASH_RANGE 4193281LL          // HASH_SIZE - 1024 + 1

// CTA tile: 128(M) x 128(N) x 32(K); one 32x32 hash tile per (stage, nb)
#define NSTAGE 256                    // 8192 / 32
#define NBT    4                      // hash n-tiles per CTA (128/32)

// Dynamic smem layout: A[2] 16KB, B[2] 16KB, starts 4KB
#define OFF_A(s)   ((s) * 16384)
#define OFF_B(s)   (32768 + (s) * 16384)
#define OFF_STARTS 65536
#define SMEM_TOTAL (65536 + NSTAGE * NBT * 4)   // 69632

// tf32-rounded copies of the inputs
__device__ float g_xr[TOKENS * DIM_K];    // 16 MB
__device__ float g_wr[HASH_SIZE];         // 16 MB

// ---------------------------------------------------------------------------
// Helpers
// ---------------------------------------------------------------------------
__device__ __forceinline__ uint32_t smem_to_u32(const void* p) {
    uint32_t a;
    asm("{ .reg .u64 t; cvta.to.shared.u64 t, %1; cvt.u32.u64 %0, t; }" : "=r"(a) : "l"(p));
    return a;
}
__device__ __forceinline__ void cp_async_16(uint32_t smem_dst, const void* gmem_src) {
    asm volatile("cp.async.cg.shared.global [%0], [%1], 16;\n" :: "r"(smem_dst), "l"(gmem_src));
}
__device__ __forceinline__ void cp_async_4(uint32_t smem_dst, const void* gmem_src) {
    asm volatile("cp.async.ca.shared.global [%0], [%1], 4;\n" :: "r"(smem_dst), "l"(gmem_src));
}
__device__ __forceinline__ void cp_async_commit() { asm volatile("cp.async.commit_group;\n"); }
template <int N>
__device__ __forceinline__ void cp_async_wait() { asm volatile("cp.async.wait_group %0;\n" :: "n"(N)); }

__device__ __forceinline__ uint32_t f2tf32(uint32_t v) {
    uint32_t r;
    asm("cvt.rna.tf32.f32 %0, %1;" : "=r"(r) : "r"(v));
    return r;
}

__device__ __forceinline__ void ldsm_x4(uint32_t (&r)[4], uint32_t addr) {
    asm volatile("ldmatrix.sync.aligned.m8n8.x4.shared.b16 {%0,%1,%2,%3}, [%4];"
                 : "=r"(r[0]), "=r"(r[1]), "=r"(r[2]), "=r"(r[3]) : "r"(addr));
}

__device__ __forceinline__ void mma_tf32(float (&c)[4], const uint32_t (&a)[4],
                                         uint32_t b0, uint32_t b1) {
    asm volatile("mma.sync.aligned.m16n8k8.row.col.f32.tf32.tf32.f32 "
                 "{%0,%1,%2,%3}, {%4,%5,%6,%7}, {%8,%9}, {%0,%1,%2,%3};"
                 : "+f"(c[0]), "+f"(c[1]), "+f"(c[2]), "+f"(c[3])
                 : "r"(a[0]), "r"(a[1]), "r"(a[2]), "r"(a[3]), "r"(b0), "r"(b1));
}

// Robust random_numbers decode (int64 vs int32 storage; values < 2^31)
__device__ __forceinline__ void decode_rn(const int* p,
                                          long long& R1, long long& R2, long long& R3) {
    if (p[1] == 0) { R1 = (unsigned)p[2]; R2 = (unsigned)p[4]; R3 = (unsigned)p[6]; }
    else           { R1 = (unsigned)p[1]; R2 = (unsigned)p[2]; R3 = (unsigned)p[3]; }
}

// ---------------------------------------------------------------------------
// Kernel 0: round fp32 -> tf32 (RN) into scratch
// ---------------------------------------------------------------------------
__global__ void tf32_round_kernel(const uint4* __restrict__ src, uint4* __restrict__ dst, int n4) {
    const int i = blockIdx.x * blockDim.x + threadIdx.x;
    if (i < n4) {
        uint4 v = src[i];
        v.x = f2tf32(v.x); v.y = f2tf32(v.y); v.z = f2tf32(v.z); v.w = f2tf32(v.w);
        dst[i] = v;
    }
}

// ---------------------------------------------------------------------------
// Kernel 1: hashed-gather tf32 HMMA GEMM
//   A smem: K-major [m][32f] rows of 128B, chunk swizzle c^(m&7)
//   B smem: n-major [n][32f] rows of 128B (transposed during gather scatter),
//           chunk swizzle c^(n&7) -> both operands feed conflict-free ldmatrix
// ---------------------------------------------------------------------------
__global__ __launch_bounds__(256, 2)
void rz_hmma_kernel(const float* __restrict__ bias,
                    const int* __restrict__ rn,
                    float* __restrict__ out) {
    extern __shared__ char smem[];
    const uint32_t smem_base = smem_to_u32(smem);
    const int tid  = threadIdx.x;
    const int lane = tid & 31;
    const int wid  = tid >> 5;
    const int wm   = wid >> 1;            // 0..3 -> 32-row warp tile
    const int wn   = wid & 1;             // 0..1 -> 64-col warp tile
    const int m0   = blockIdx.y * 128;
    const int n0   = blockIdx.x * 128;

    // Precompute hash tile starts: starts[stage][nb]
    int (*starts)[NBT] = (int (*)[NBT])(smem + OFF_STARTS);
    {
        long long R1, R2, R3;
        decode_rn(rn, R1, R2, R3);
        const long long ntb = blockIdx.x * NBT;
        for (int i = tid; i < NSTAGE * NBT; i += 256) {
            const int kt = i >> 2, nb = i & 3;
            long long v = ((long long)kt * R3 + (ntb + nb) * R2 + R1) % P_HASH;
            starts[kt][nb] = (int)(v % HASH_RANGE);
        }
    }
    __syncthreads();

    // Stage loader
    auto issue = [&](int t) {
        const int slot = t & 1;
        const uint32_t As = smem_base + OFF_A(slot);
        const uint32_t Bs = smem_base + OFF_B(slot);
        const float* xr = g_xr + (size_t)m0 * DIM_K + t * 32;
#pragma unroll
        for (int u = 0; u < 4; u++) {               // A: 1024 x 16B chunks
            const int ch = tid + u * 256;
            const int m = ch >> 3, c = ch & 7;
            cp_async_16(As + m * 128 + ((c ^ (m & 7)) << 4),
                        xr + (size_t)m * DIM_K + c * 4);
        }
#pragma unroll
        for (int u = 0; u < 16; u++) {              // B: 4096 x 4B (transpose scatter)
            const int e = tid + u * 256;
            const int k = e >> 7, n = e & 127;
            cp_async_4(Bs + n * 128 + ((((k >> 2) ^ (n & 7))) << 4) + (k & 3) * 4,
                       g_wr + starts[t][n >> 5] + k * 32 + (n & 31));
        }
        cp_async_commit();
    };

    float acc[2][8][4];
#pragma unroll
    for (int mt = 0; mt < 2; mt++)
#pragma unroll
        for (int nt = 0; nt < 8; nt++)
#pragma unroll
            for (int j = 0; j < 4; j++) acc[mt][nt][j] = 0.0f;

    const int q = lane >> 3, r8 = lane & 7;

    issue(0);

    for (int t = 0; t < NSTAGE; t++) {
        if (t + 1 < NSTAGE) { issue(t + 1); cp_async_wait<1>(); }
        else                { cp_async_wait<0>(); }
        __syncthreads();

        const uint32_t As = smem_base + OFF_A(t & 1);
        const uint32_t Bs = smem_base + OFF_B(t & 1);
#pragma unroll
        for (int g = 0; g < 4; g++) {               // k8 steps
            uint32_t a[2][4];
#pragma unroll
            for (int mt = 0; mt < 2; mt++) {
                const int mrow = wm * 32 + mt * 16 + ((q & 1) << 3) + r8;
                const int ch = (g << 1) + (q >> 1);
                ldsm_x4(a[mt], As + mrow * 128 + ((ch ^ (mrow & 7)) << 4));
            }
            uint32_t b[4][4];
#pragma unroll
            for (int nt2 = 0; nt2 < 4; nt2++) {
                const int nrow = wn * 64 + nt2 * 16 + ((q >> 1) << 3) + r8;
                const int ch = (g << 1) + (q & 1);
                ldsm_x4(b[nt2], Bs + nrow * 128 + ((ch ^ (nrow & 7)) << 4));
            }
#pragma unroll
            for (int mt = 0; mt < 2; mt++)
#pragma unroll
                for (int nt = 0; nt < 8; nt++)
                    mma_tf32(acc[mt][nt], a[mt],
                             b[nt >> 1][(nt & 1) * 2], b[nt >> 1][(nt & 1) * 2 + 1]);
        }
        __syncthreads();
    }

    // Epilogue: c0/c1 at (row=lane>>2, col=2*(lane&3)), c2/c3 at row+8
#pragma unroll
    for (int mt = 0; mt < 2; mt++) {
#pragma unroll
        for (int nt = 0; nt < 8; nt++) {
            const int m = m0 + wm * 32 + mt * 16 + (lane >> 2);
            const int n = n0 + wn * 64 + nt * 8 + (lane & 3) * 2;
            const float2 b = *(const float2*)&bias[n];
            float2 o0, o1;
            o0.x = acc[mt][nt][0] + b.x;  o0.y = acc[mt][nt][1] + b.y;
            o1.x = acc[mt][nt][2] + b.x;  o1.y = acc[mt][nt][3] + b.y;
            *(float2*)&out[(size_t)m * DIM_N + n]       = o0;
            *(float2*)&out[(size_t)(m + 8) * DIM_N + n] = o1;
        }
    }
}

// ---------------------------------------------------------------------------
// Launch
// ---------------------------------------------------------------------------
extern "C" void kernel_launch(void* const* d_in, const int* in_sizes, int n_in,
                              void* d_out, int out_size) {
    const float* x    = (const float*)d_in[0];
    const float* hw   = (const float*)d_in[1];
    const float* bias = (const float*)d_in[2];
    const int*   rn   = (const int*)d_in[3];
    float*       out  = (float*)d_out;

    float* xr; cudaGetSymbolAddress((void**)&xr, g_xr);
    float* wr; cudaGetSymbolAddress((void**)&wr, g_wr);

    const int n4x = TOKENS * DIM_K / 4;
    const int n4w = HASH_SIZE / 4;
    tf32_round_kernel<<<(n4x + 255) / 256, 256>>>((const uint4*)x, (uint4*)xr, n4x);
    tf32_round_kernel<<<(n4w + 255) / 256, 256>>>((const uint4*)hw, (uint4*)wr, n4w);

    cudaFuncSetAttribute(rz_hmma_kernel, cudaFuncAttributeMaxDynamicSharedMemorySize, SMEM_TOTAL);
    rz_hmma_kernel<<<dim3(DIM_N / 128, TOKENS / 128), 256, SMEM_TOTAL>>>(bias, rn, out);
}

// round 6
// speedup vs baseline: 3.4395x; 1.9663x over previous
#include <cuda_runtime.h>
#include <cstdint>

// ---------------------------------------------------------------------------
// Problem constants
// ---------------------------------------------------------------------------
#define TOKENS     512
#define DIM_K      8192
#define DIM_N      8192
#define HASH_SIZE  (1 << 22)
#define P_HASH     2038074743LL
#define HASH_RANGE 4193281LL          // HASH_SIZE - 1024 + 1

// CTA tile: 256(M) x 128(N) x 32(K); 4 hash tiles per stage
#define NSTAGE 256                    // 8192 / 32
#define NBT    4
#define THREADS 512

// smem layout: 4-stage pipeline
//   A stage: 256 rows x 128B (swizzled K-major)              = 32768 B
//   B stage: 4 tiles x 32 k-rows x 160B pitch (shifted n)    = 20480 B
#define OFF_A(s)   ((s) * 32768)
#define OFF_B(s)   (131072 + (s) * 20480)
#define OFF_STARTS 212992
#define SMEM_TOTAL (212992 + NSTAGE * NBT * 4)   // 217088

// tf32-rounded copies of the inputs
__device__ float g_xr[TOKENS * DIM_K];    // 16 MB
__device__ float g_wr[HASH_SIZE];         // 16 MB

// ---------------------------------------------------------------------------
// Helpers
// ---------------------------------------------------------------------------
__device__ __forceinline__ uint32_t smem_to_u32(const void* p) {
    uint32_t a;
    asm("{ .reg .u64 t; cvta.to.shared.u64 t, %1; cvt.u32.u64 %0, t; }" : "=r"(a) : "l"(p));
    return a;
}
__device__ __forceinline__ void cp_async_16(uint32_t smem_dst, const void* gmem_src) {
    asm volatile("cp.async.cg.shared.global [%0], [%1], 16;\n" :: "r"(smem_dst), "l"(gmem_src));
}
__device__ __forceinline__ void cp_async_16p(uint32_t smem_dst, const void* gmem_src, bool pred) {
    if (pred) cp_async_16(smem_dst, gmem_src);
}
__device__ __forceinline__ void cp_async_4(uint32_t smem_dst, const void* gmem_src) {
    asm volatile("cp.async.ca.shared.global [%0], [%1], 4;\n" :: "r"(smem_dst), "l"(gmem_src));
}
__device__ __forceinline__ void cp_async_commit() { asm volatile("cp.async.commit_group;\n"); }
template <int N>
__device__ __forceinline__ void cp_async_wait() { asm volatile("cp.async.wait_group %0;\n" :: "n"(N)); }

__device__ __forceinline__ uint32_t f2tf32(uint32_t v) {
    uint32_t r;
    asm("cvt.rna.tf32.f32 %0, %1;" : "=r"(r) : "r"(v));
    return r;
}
__device__ __forceinline__ void ldsm_x4(uint32_t (&r)[4], uint32_t addr) {
    asm volatile("ldmatrix.sync.aligned.m8n8.x4.shared.b16 {%0,%1,%2,%3}, [%4];"
                 : "=r"(r[0]), "=r"(r[1]), "=r"(r[2]), "=r"(r[3]) : "r"(addr));
}
__device__ __forceinline__ void mma_tf32(float (&c)[4], const uint32_t (&a)[4],
                                         uint32_t b0, uint32_t b1) {
    asm volatile("mma.sync.aligned.m16n8k8.row.col.f32.tf32.tf32.f32 "
                 "{%0,%1,%2,%3}, {%4,%5,%6,%7}, {%8,%9}, {%0,%1,%2,%3};"
                 : "+f"(c[0]), "+f"(c[1]), "+f"(c[2]), "+f"(c[3])
                 : "r"(a[0]), "r"(a[1]), "r"(a[2]), "r"(a[3]), "r"(b0), "r"(b1));
}

// Robust random_numbers decode (int64 vs int32 storage; values < 2^31)
__device__ __forceinline__ void decode_rn(const int* p,
                                          long long& R1, long long& R2, long long& R3) {
    if (p[1] == 0) { R1 = (unsigned)p[2]; R2 = (unsigned)p[4]; R3 = (unsigned)p[6]; }
    else           { R1 = (unsigned)p[1]; R2 = (unsigned)p[2]; R3 = (unsigned)p[3]; }
}

// ---------------------------------------------------------------------------
// Kernel 0: round fp32 -> tf32 (RN) into scratch
// ---------------------------------------------------------------------------
__global__ void tf32_round_kernel(const uint4* __restrict__ src, uint4* __restrict__ dst, int n4) {
    const int i = blockIdx.x * blockDim.x + threadIdx.x;
    if (i < n4) {
        uint4 v = src[i];
        v.x = f2tf32(v.x); v.y = f2tf32(v.y); v.z = f2tf32(v.z); v.w = f2tf32(v.w);
        dst[i] = v;
    }
}

// ---------------------------------------------------------------------------
// Kernel 1: hashed-gather tf32 HMMA GEMM, 16B-chunked B gather.
//   B smem per tile: k-major, pitch 160B, element (k,n) at k*160+((n-h)&31)*4
//   where h = (4 - start%4) & 3 -> 16B chunks land aligned; fragment LDS
//   banks = (8k + n') % 32, conflict-free.
// ---------------------------------------------------------------------------
__global__ __launch_bounds__(THREADS, 1)
void rz_hmma_kernel(const float* __restrict__ bias,
                    const int* __restrict__ rn,
                    float* __restrict__ out) {
    extern __shared__ char smem[];
    const uint32_t smem_base = smem_to_u32(smem);
    const int tid  = threadIdx.x;
    const int lane = tid & 31;
    const int wid  = tid >> 5;         // 0..15
    const int wm   = wid >> 2;         // 0..3: 64-row warp tile
    const int wn   = wid & 3;          // 0..3: 32-col warp tile (= hash tile)
    const int m0   = blockIdx.y * 256;
    const int n0   = blockIdx.x * 128;

    // Precompute hash tile starts
    int (*starts)[NBT] = (int (*)[NBT])(smem + OFF_STARTS);
    {
        long long R1, R2, R3;
        decode_rn(rn, R1, R2, R3);
        const long long ntb = blockIdx.x * NBT;
        for (int i = tid; i < NSTAGE * NBT; i += THREADS) {
            const int kt = i >> 2, nb = i & 3;
            long long v = ((long long)kt * R3 + (ntb + nb) * R2 + R1) % P_HASH;
            starts[kt][nb] = (int)(v % HASH_RANGE);
        }
    }
    __syncthreads();

    const int btile = tid >> 7;        // 0..3: tile this thread loads
    const int t128  = tid & 127;

    auto issue = [&](int t) {
        const int slot = t & 3;
        const uint32_t As = smem_base + OFF_A(slot);
        // ---- A: 2048 x 16B swizzled K-major chunks ----
        const float* xa = g_xr + (size_t)m0 * DIM_K + t * 32;
#pragma unroll
        for (int u = 0; u < 4; u++) {
            const int ch = tid + u * THREADS;
            const int m = ch >> 3, c = ch & 7;
            cp_async_16(As + m * 128 + ((c ^ (m & 7)) << 4),
                        xa + (size_t)m * DIM_K + c * 4);
        }
        // ---- B: one hash tile per 128 threads, 16B chunks + head/tail ----
        const int S = starts[t][btile];
        const int h = (4 - (S & 3)) & 3;
        const float* src = g_wr + S;
        const uint32_t Bt = smem_base + OFF_B(slot) + btile * 5120;
        const int nch = h ? 7 : 8;
#pragma unroll
        for (int u = 0; u < 2; u++) {
            const int c = t128 + (u << 7);
            const int r = c >> 3, s = c & 7;
            cp_async_16p(Bt + r * 160 + s * 16, src + 32 * r + h + 4 * s, s < nch);
        }
        if (h) {
            const int r = t128 >> 2, j = t128 & 3;
            const int n4 = (j < h) ? j : j + 28;
            cp_async_4(Bt + r * 160 + (((n4 - h) & 31) << 2), src + 32 * r + n4);
        }
    };

    float acc[4][4][4];
#pragma unroll
    for (int mt = 0; mt < 4; mt++)
#pragma unroll
        for (int nt = 0; nt < 4; nt++)
#pragma unroll
            for (int j = 0; j < 4; j++) acc[mt][nt][j] = 0.0f;

    const int q = lane >> 3, r8 = lane & 7;

    issue(0); cp_async_commit();
    issue(1); cp_async_commit();
    issue(2); cp_async_commit();

    for (int t = 0; t < NSTAGE; t++) {
        if (t + 3 < NSTAGE) issue(t + 3);
        cp_async_commit();
        cp_async_wait<3>();
        __syncthreads();

        const int slot = t & 3;
        const uint32_t As = smem_base + OFF_A(slot);
        const uint32_t Bw = smem_base + OFF_B(slot) + wn * 5120;
        const int hcur = (4 - (starts[t][wn] & 3)) & 3;
#pragma unroll
        for (int g = 0; g < 4; g++) {
            uint32_t a[4][4];
#pragma unroll
            for (int mt = 0; mt < 4; mt++) {
                const int mrow = wm * 64 + mt * 16 + ((q & 1) << 3) + r8;
                const int ch = (g << 1) + (q >> 1);
                ldsm_x4(a[mt], As + mrow * 128 + ((ch ^ (mrow & 7)) << 4));
            }
#pragma unroll
            for (int nt = 0; nt < 4; nt++) {
                const int nlog = nt * 8 + (lane >> 2);
                const uint32_t ba = Bw + (g * 8 + (lane & 3)) * 160
                                       + (((nlog - hcur) & 31) << 2);
                const uint32_t b0 = *(const uint32_t*)(smem + (ba - smem_base));
                const uint32_t b1 = *(const uint32_t*)(smem + (ba + 640 - smem_base));
#pragma unroll
                for (int mt = 0; mt < 4; mt++)
                    mma_tf32(acc[mt][nt], a[mt], b0, b1);
            }
        }
        __syncthreads();
    }

    // Epilogue
#pragma unroll
    for (int mt = 0; mt < 4; mt++) {
#pragma unroll
        for (int nt = 0; nt < 4; nt++) {
            const int m = m0 + wm * 64 + mt * 16 + (lane >> 2);
            const int n = n0 + wn * 32 + nt * 8 + (lane & 3) * 2;
            const float2 b = *(const float2*)&bias[n];
            float2 o0, o1;
            o0.x = acc[mt][nt][0] + b.x;  o0.y = acc[mt][nt][1] + b.y;
            o1.x = acc[mt][nt][2] + b.x;  o1.y = acc[mt][nt][3] + b.y;
            *(float2*)&out[(size_t)m * DIM_N + n]       = o0;
            *(float2*)&out[(size_t)(m + 8) * DIM_N + n] = o1;
        }
    }
}

// ---------------------------------------------------------------------------
// Launch
// ---------------------------------------------------------------------------
extern "C" void kernel_launch(void* const* d_in, const int* in_sizes, int n_in,
                              void* d_out, int out_size) {
    const float* x    = (const float*)d_in[0];
    const float* hw   = (const float*)d_in[1];
    const float* bias = (const float*)d_in[2];
    const int*   rn   = (const int*)d_in[3];
    float*       out  = (float*)d_out;

    float* xr; cudaGetSymbolAddress((void**)&xr, g_xr);
    float* wr; cudaGetSymbolAddress((void**)&wr, g_wr);

    const int n4x = TOKENS * DIM_K / 4;
    const int n4w = HASH_SIZE / 4;
    tf32_round_kernel<<<(n4x + 255) / 256, 256>>>((const uint4*)x, (uint4*)xr, n4x);
    tf32_round_kernel<<<(n4w + 255) / 256, 256>>>((const uint4*)hw, (uint4*)wr, n4w);

    cudaFuncSetAttribute(rz_hmma_kernel, cudaFuncAttributeMaxDynamicSharedMemorySize, SMEM_TOTAL);
    rz_hmma_kernel<<<dim3(DIM_N / 128, TOKENS / 256), THREADS, SMEM_TOTAL>>>(bias, rn, out);
}